// round 15
// baseline (speedup 1.0000x reference)
#include <cuda_runtime.h>
#include <cuda_bf16.h>
#include <cstdint>

// Problem constants
#define BSZ 2
#define QL 512
#define KLEN 8192
#define DMODEL 1024
#define NH 8
#define HD 128

// Scratch (allocation-free rule: __device__ globals)
__device__ __nv_bfloat16 g_Xqh[BSZ * QL * DMODEL],  g_Xql[BSZ * QL * DMODEL];
__device__ __nv_bfloat16 g_Xkh[BSZ * KLEN * DMODEL], g_Xkl[BSZ * KLEN * DMODEL];
__device__ __nv_bfloat16 g_Xvh[BSZ * KLEN * DMODEL], g_Xvl[BSZ * KLEN * DMODEL];
__device__ __nv_bfloat16 g_Wqh[DMODEL * DMODEL], g_Wql[DMODEL * DMODEL];
__device__ __nv_bfloat16 g_Wkh[DMODEL * DMODEL], g_Wkl[DMODEL * DMODEL];
__device__ __nv_bfloat16 g_Wvh[DMODEL * DMODEL], g_Wvl[DMODEL * DMODEL];
__device__ __nv_bfloat16 g_Wfh[DMODEL * DMODEL], g_Wfl[DMODEL * DMODEL];
__device__ __nv_bfloat16 g_Qh[BSZ * QL * DMODEL],  g_Ql[BSZ * QL * DMODEL];
__device__ __nv_bfloat16 g_Kh[BSZ * KLEN * DMODEL], g_Kl[BSZ * KLEN * DMODEL];
__device__ __nv_bfloat16 g_Vh[BSZ * KLEN * DMODEL], g_Vl[BSZ * KLEN * DMODEL];
__device__ __nv_bfloat16 g_Ah[BSZ * QL * DMODEL],  g_Al[BSZ * QL * DMODEL];

// ===========================================================================
// Helpers
// ===========================================================================
__device__ __forceinline__ uint32_t smem_u32(const void* p) {
    uint32_t a;
    asm("{ .reg .u64 t; cvta.to.shared.u64 t, %1; cvt.u32.u64 %0, t; }"
        : "=r"(a) : "l"(p));
    return a;
}

__device__ __forceinline__ void mma_bf16(float* d, const uint32_t* a,
                                         uint32_t b0, uint32_t b1) {
    asm volatile(
        "mma.sync.aligned.m16n8k16.row.col.f32.bf16.bf16.f32 "
        "{%0,%1,%2,%3}, {%4,%5,%6,%7}, {%8,%9}, {%0,%1,%2,%3};"
        : "+f"(d[0]), "+f"(d[1]), "+f"(d[2]), "+f"(d[3])
        : "r"(a[0]), "r"(a[1]), "r"(a[2]), "r"(a[3]), "r"(b0), "r"(b1));
}

__device__ __forceinline__ void ldsm4(uint32_t* r, uint32_t addr) {
    asm volatile("ldmatrix.sync.aligned.m8n8.x4.shared.b16 {%0,%1,%2,%3}, [%4];"
                 : "=r"(r[0]), "=r"(r[1]), "=r"(r[2]), "=r"(r[3]) : "r"(addr));
}

__device__ __forceinline__ void ldsm4t(uint32_t* r, uint32_t addr) {
    asm volatile("ldmatrix.sync.aligned.m8n8.x4.trans.shared.b16 {%0,%1,%2,%3}, [%4];"
                 : "=r"(r[0]), "=r"(r[1]), "=r"(r[2]), "=r"(r[3]) : "r"(addr));
}

__device__ __forceinline__ uint32_t pack_hi(float x, float y, uint32_t& lo) {
    __nv_bfloat162 h = __float22bfloat162_rn(make_float2(x, y));
    float2 f = __bfloat1622float2(h);
    __nv_bfloat162 l = __float22bfloat162_rn(make_float2(x - f.x, y - f.y));
    lo = *reinterpret_cast<uint32_t*>(&l);
    return *reinterpret_cast<uint32_t*>(&h);
}

__device__ __forceinline__ void cp16(uint32_t dst, const void* src) {
    asm volatile("cp.async.cg.shared.global [%0], [%1], 16;" :: "r"(dst), "l"(src));
}
#define CP_COMMIT() asm volatile("cp.async.commit_group;")
#define CP_WAIT(n)  asm volatile("cp.async.wait_group %0;" :: "n"(n))

// Named barriers (producer/consumer). Count = 288 threads (9 warps).
#define NBAR_SYNC(id)   asm volatile("bar.sync %0, 288;"   :: "r"(id) : "memory")
#define NBAR_ARRIVE(id) asm volatile("bar.arrive %0, 288;" :: "r"(id) : "memory")

// ===========================================================================
// Split: fp32 -> (hi bf16, lo bf16), MLP=4 superstep
// ===========================================================================
__global__ __launch_bounds__(256) void split_f32(
    const float* __restrict__ in, __nv_bfloat16* __restrict__ oh,
    __nv_bfloat16* __restrict__ ol, int n4)
{
    const int stride = gridDim.x * blockDim.x;
    for (int i = blockIdx.x * blockDim.x + threadIdx.x; i < n4; i += 4 * stride) {
        float4 v[4];
        int idx[4];
        int cnt = 0;
#pragma unroll
        for (int j = 0; j < 4; j++) {
            int ii = i + j * stride;
            if (ii < n4) { v[cnt] = ((const float4*)in)[ii]; idx[cnt] = ii; cnt++; }
        }
#pragma unroll
        for (int j = 0; j < 4; j++) {
            if (j < cnt) {
                uint32_t l0, l1;
                uint32_t h0 = pack_hi(v[j].x, v[j].y, l0);
                uint32_t h1 = pack_hi(v[j].z, v[j].w, l1);
                ((uint2*)oh)[idx[j]] = make_uint2(h0, h1);
                ((uint2*)ol)[idx[j]] = make_uint2(l0, l1);
            }
        }
    }
}

// ===========================================================================
// Split-bf16 GEMM, cp.async 3-stage pipeline, 2 CTAs/SM. (unchanged)
// ===========================================================================
#define G_STAGE 32768
#define G_SMEM  (3 * G_STAGE)

__device__ __forceinline__ uint32_t g_ldaddr(uint32_t base, int row0, int chunk0, int lane) {
    int r = row0 + (lane & 7) + ((lane >> 3) & 1) * 8;
    int c = (chunk0 + (lane >> 4)) ^ ((r >> 1) & 3);
    return base + (uint32_t)(r * 4 + c) * 16;
}

__device__ __forceinline__ void gemm_stage(
    uint32_t sb, int st, int kt, int tid, int bm, int bn, int K,
    const __nv_bfloat16* Ah, const __nv_bfloat16* Al,
    const __nv_bfloat16* Bh, const __nv_bfloat16* Bl)
{
#pragma unroll
    for (int i = 0; i < 8; i++) {
        int ci = tid + i * 256;
        int arr = ci >> 9, cj = ci & 511;
        int row = cj >> 2, c = cj & 3;
        const __nv_bfloat16* g = (arr == 0) ? Ah : (arr == 1) ? Al
                               : (arr == 2) ? Bh : Bl;
        int rb = (arr < 2) ? bm : bn;
        const void* src = g + (size_t)(rb + row) * K + kt + c * 8;
        uint32_t dst = sb + st * G_STAGE + arr * 8192 +
                       (uint32_t)((row << 2) + (c ^ ((row >> 1) & 3))) * 16;
        cp16(dst, src);
    }
    CP_COMMIT();
}

template <bool SPLIT_OUT>
__global__ __launch_bounds__(256, 2) void gemm_bs(
    const __nv_bfloat16* __restrict__ Ah, const __nv_bfloat16* __restrict__ Al,
    const __nv_bfloat16* __restrict__ Bh, const __nv_bfloat16* __restrict__ Bl,
    const float* __restrict__ bias, float* __restrict__ C,
    __nv_bfloat16* __restrict__ Ch, __nv_bfloat16* __restrict__ Cl,
    int M, int N, int K)
{
    extern __shared__ char smem[];
    const uint32_t sb = smem_u32(smem);
    const int tid = threadIdx.x;
    const int lane = tid & 31, warp = tid >> 5;
    const int wm = warp >> 2, wn = warp & 3;
    const int bm = blockIdx.y * 128, bn = blockIdx.x * 128;

    float acc[4][4][4];
#pragma unroll
    for (int i = 0; i < 4; i++)
#pragma unroll
        for (int j = 0; j < 4; j++)
#pragma unroll
            for (int q = 0; q < 4; q++) acc[i][j][q] = 0.0f;

    const int S = K / 32;
    gemm_stage(sb, 0, 0, tid, bm, bn, K, Ah, Al, Bh, Bl);
    gemm_stage(sb, 1, 32, tid, bm, bn, K, Ah, Al, Bh, Bl);

    for (int s = 0; s < S; s++) {
        if (s + 1 < S) { CP_WAIT(1); } else { CP_WAIT(0); }
        __syncthreads();
        if (s + 2 < S)
            gemm_stage(sb, (s + 2) % 3, (s + 2) * 32, tid, bm, bn, K, Ah, Al, Bh, Bl);

        const uint32_t stb = sb + (s % 3) * G_STAGE;
        const uint32_t aAh = stb, aAl = stb + 8192;
        const uint32_t aBh = stb + 16384, aBl = stb + 24576;
#pragma unroll
        for (int ks = 0; ks < 2; ks++) {
            uint32_t ah[4][4], al[4][4], bh[2][4], bl[2][4];
#pragma unroll
            for (int am = 0; am < 4; am++) {
                ldsm4(ah[am], g_ldaddr(aAh, wm * 64 + am * 16, ks * 2, lane));
                ldsm4(al[am], g_ldaddr(aAl, wm * 64 + am * 16, ks * 2, lane));
            }
#pragma unroll
            for (int nb = 0; nb < 2; nb++) {
                ldsm4(bh[nb], g_ldaddr(aBh, wn * 32 + nb * 16, ks * 2, lane));
                ldsm4(bl[nb], g_ldaddr(aBl, wn * 32 + nb * 16, ks * 2, lane));
            }
#pragma unroll
            for (int am = 0; am < 4; am++)
#pragma unroll
                for (int an = 0; an < 4; an++) {
                    const int nb = an >> 1, si = an & 1;
                    mma_bf16(acc[am][an], ah[am], bh[nb][si], bh[nb][si + 2]);
                    mma_bf16(acc[am][an], ah[am], bl[nb][si], bl[nb][si + 2]);
                    mma_bf16(acc[am][an], al[am], bh[nb][si], bh[nb][si + 2]);
                }
        }
    }

#pragma unroll
    for (int am = 0; am < 4; am++) {
        const int r0 = bm + wm * 64 + am * 16 + (lane >> 2);
#pragma unroll
        for (int an = 0; an < 4; an++) {
            const int col = bn + wn * 32 + an * 8 + (lane & 3) * 2;
            float2 b01 = *(const float2*)&bias[col];
            float v0 = acc[am][an][0] + b01.x, v1 = acc[am][an][1] + b01.y;
            float v2 = acc[am][an][2] + b01.x, v3 = acc[am][an][3] + b01.y;
            if (SPLIT_OUT) {
                uint32_t lo0, lo1;
                uint32_t h0 = pack_hi(v0, v1, lo0);
                uint32_t h1 = pack_hi(v2, v3, lo1);
                *(uint32_t*)&Ch[(size_t)r0 * N + col] = h0;
                *(uint32_t*)&Cl[(size_t)r0 * N + col] = lo0;
                *(uint32_t*)&Ch[(size_t)(r0 + 8) * N + col] = h1;
                *(uint32_t*)&Cl[(size_t)(r0 + 8) * N + col] = lo1;
            } else {
                *(float2*)&C[(size_t)r0 * N + col] = make_float2(v0, v1);
                *(float2*)&C[(size_t)(r0 + 8) * N + col] = make_float2(v2, v3);
            }
        }
    }
}

// ===========================================================================
// Tensor-core flash attention, WARP-SPECIALIZED:
// 8 consumer warps (4 row-groups x 2 key-halves) + 1 producer warp that owns
// all cp.async K/V fills. Sync via named barriers (FULL ids 1-3, FREE 4-6);
// NO __syncthreads in the mainloop. Fixed-max softmax.
// ===========================================================================
#define ATT_THREADS 288   // 9 warps
#define ATT_Q_H 0
#define ATT_Q_L 16384
#define ATT_ST0 32768
#define ATT_STAGE 65536
#define ATT_SMEM (32768 + 3 * ATT_STAGE)   // 224 KB
#define ATT_O_MERGE 32768   // fp32 [64][128] overlay after mainloop

__device__ __forceinline__ uint32_t taddr(uint32_t base, int r, int c) {
    return base + (uint32_t)((r << 4) + (c ^ (r & 7))) * 16;
}
__device__ __forceinline__ uint32_t ab_addr(uint32_t base, int row0, int c0, int lane) {
    int r = row0 + (lane & 7) + ((lane >> 3) & 1) * 8;
    int c = c0 + (lane >> 4);
    return taddr(base, r, c);
}
__device__ __forceinline__ uint32_t v_addr(uint32_t base, int row0, int c0, int lane) {
    int r = row0 + (lane & 15);
    int c = c0 + (lane >> 4);
    return taddr(base, r, c);
}

// Producer fill: one warp copies the whole 64KB stage.
// 4 arrays x 1024 16B-chunks = 4096 chunks; 32 lanes -> 128 cp16 per lane.
// (Round-14 bug: this loop ran to 64, filling only K — V was garbage -> NaN.)
__device__ __forceinline__ void attn_fill(
    uint32_t sb, int st, int k0, int lane, int b, int h,
    const __nv_bfloat16* Kh, const __nv_bfloat16* Kl,
    const __nv_bfloat16* Vh, const __nv_bfloat16* Vl)
{
#pragma unroll
    for (int j = 0; j < 128; j++) {
        int ci = lane + j * 32;      // 0..4095
        int arr = ci >> 10;          // 0..3 (compile-time per j)
        int cj = ci & 1023;
        int row = cj >> 4, c = cj & 15;
        const __nv_bfloat16* g = (arr == 0) ? Kh : (arr == 1) ? Kl
                               : (arr == 2) ? Vh : Vl;
        const void* src = g + (size_t)(b * KLEN + k0 + row) * DMODEL + h * HD + c * 8;
        uint32_t dst = sb + ATT_ST0 + st * ATT_STAGE + arr * 16384 +
                       (uint32_t)((row << 4) + (c ^ (row & 7))) * 16;
        cp16(dst, src);
    }
    CP_COMMIT();
}

__global__ __launch_bounds__(ATT_THREADS) void attn_tc(
    const __nv_bfloat16* __restrict__ Qh, const __nv_bfloat16* __restrict__ Ql,
    const __nv_bfloat16* __restrict__ Kh, const __nv_bfloat16* __restrict__ Kl,
    const __nv_bfloat16* __restrict__ Vh, const __nv_bfloat16* __restrict__ Vl,
    const unsigned int* __restrict__ mask,
    __nv_bfloat16* __restrict__ Oh, __nv_bfloat16* __restrict__ Ol)
{
    extern __shared__ char smem[];
    __shared__ float sm_l[2][64];
    const uint32_t sb = smem_u32(smem);
    const int tid = threadIdx.x, lane = tid & 31, warp = tid >> 5;
    const int rg = warp & 3, khf = warp >> 2;   // valid for warps 0-7
    const int b = blockIdx.z, h = blockIdx.y;
    const int q0 = blockIdx.x * 64;
    const int S = KLEN / 64;

    // stage Q hi/lo (all 9 warps help)
    for (int ci = tid; ci < 1024; ci += ATT_THREADS) {
        int r = ci >> 4, c = ci & 15;
        size_t g = ((size_t)(b * QL + q0 + r) * DMODEL + h * HD) / 8 + c;
        uint32_t d = (uint32_t)((r << 4) + (c ^ (r & 7))) * 16;
        *(uint4*)(smem + ATT_Q_H + d) = ((const uint4*)Qh)[g];
        *(uint4*)(smem + ATT_Q_L + d) = ((const uint4*)Ql)[g];
    }
    __syncthreads();

    float l0 = 0.0f, l1 = 0.0f;
    float o[16][4];
    const int r_lo = rg * 16 + (lane >> 2);

    if (warp < 8) {
        // ---------------- consumer warps ----------------
        uint32_t qhr[8][4];
#pragma unroll
        for (int ks = 0; ks < 8; ks++)
            ldsm4(qhr[ks], ab_addr(sb + ATT_Q_H, rg * 16, ks * 2, lane));

#pragma unroll
        for (int n = 0; n < 16; n++)
#pragma unroll
            for (int j = 0; j < 4; j++) o[n][j] = 0.0f;
        const float scale2 = 0.08838834764831845f * 1.4426950408889634f;
        const float FIXM = 16.0f;

        const unsigned int* mrow0 = mask + (size_t)(b * QL + q0 + r_lo) * KLEN;
        const unsigned int* mrow1 = mrow0 + 8 * (size_t)KLEN;

        for (int s = 0; s < S; s++) {
            const int k0 = s * 64;

            // mask loads issued before the FULL wait (overlap LDG w/ waiting)
            uint2 mka[4], mkb[4];
#pragma unroll
            for (int an = 0; an < 4; an++) {
                int col = k0 + khf * 32 + an * 8 + (lane & 3) * 2;
                mka[an] = *(const uint2*)&mrow0[col];
                mkb[an] = *(const uint2*)&mrow1[col];
            }

            NBAR_SYNC(1 + s % 3);   // wait stage full

            const uint32_t stb = sb + ATT_ST0 + (s % 3) * ATT_STAGE;
            const uint32_t aKh = stb, aKl = stb + 16384;
            const uint32_t aVh = stb + 32768, aVl = stb + 49152;

            // ---- QK^T, split 3-term ----
            float s4[4][4];
#pragma unroll
            for (int an = 0; an < 4; an++)
#pragma unroll
                for (int j = 0; j < 4; j++) s4[an][j] = 0.0f;

#pragma unroll
            for (int ks = 0; ks < 8; ks++) {
                uint32_t ql4[4], kbh0[4], kbh1[4], kbl0[4], kbl1[4];
                ldsm4(ql4, ab_addr(sb + ATT_Q_L, rg * 16, ks * 2, lane));
                ldsm4(kbh0, ab_addr(aKh, khf * 32, ks * 2, lane));
                ldsm4(kbh1, ab_addr(aKh, khf * 32 + 16, ks * 2, lane));
                ldsm4(kbl0, ab_addr(aKl, khf * 32, ks * 2, lane));
                ldsm4(kbl1, ab_addr(aKl, khf * 32 + 16, ks * 2, lane));
#pragma unroll
                for (int an = 0; an < 4; an++) {
                    const uint32_t* bh = (an < 2) ? kbh0 : kbh1;
                    const uint32_t* bl = (an < 2) ? kbl0 : kbl1;
                    const int si = an & 1;
                    mma_bf16(s4[an], qhr[ks], bh[si], bh[si + 2]);
                    mma_bf16(s4[an], qhr[ks], bl[si], bl[si + 2]);
                    mma_bf16(s4[an], ql4, bh[si], bh[si + 2]);
                }
            }

            // ---- fixed-max softmax ----
            float ps0 = 0.0f, ps1 = 0.0f;
#pragma unroll
            for (int an = 0; an < 4; an++) {
                s4[an][0] = mka[an].x ? exp2f(fmaf(s4[an][0], scale2, -FIXM)) : 0.0f;
                s4[an][1] = mka[an].y ? exp2f(fmaf(s4[an][1], scale2, -FIXM)) : 0.0f;
                s4[an][2] = mkb[an].x ? exp2f(fmaf(s4[an][2], scale2, -FIXM)) : 0.0f;
                s4[an][3] = mkb[an].y ? exp2f(fmaf(s4[an][3], scale2, -FIXM)) : 0.0f;
                ps0 += s4[an][0] + s4[an][1];
                ps1 += s4[an][2] + s4[an][3];
            }
            ps0 += __shfl_xor_sync(0xffffffffu, ps0, 1);
            ps0 += __shfl_xor_sync(0xffffffffu, ps0, 2);
            ps1 += __shfl_xor_sync(0xffffffffu, ps1, 1);
            ps1 += __shfl_xor_sync(0xffffffffu, ps1, 2);
            l0 += ps0; l1 += ps1;

            // ---- P @ V, split 3-term ----
#pragma unroll
            for (int ks2 = 0; ks2 < 2; ks2++) {
                uint32_t pah[4], pal[4];
                pah[0] = pack_hi(s4[ks2 * 2][0], s4[ks2 * 2][1], pal[0]);
                pah[1] = pack_hi(s4[ks2 * 2][2], s4[ks2 * 2][3], pal[1]);
                pah[2] = pack_hi(s4[ks2 * 2 + 1][0], s4[ks2 * 2 + 1][1], pal[2]);
                pah[3] = pack_hi(s4[ks2 * 2 + 1][2], s4[ks2 * 2 + 1][3], pal[3]);
#pragma unroll
                for (int nc = 0; nc < 8; nc++) {
                    uint32_t vh4[4], vl4[4];
                    ldsm4t(vh4, v_addr(aVh, khf * 32 + ks2 * 16, nc * 2, lane));
                    ldsm4t(vl4, v_addr(aVl, khf * 32 + ks2 * 16, nc * 2, lane));
                    mma_bf16(o[nc * 2], pah, vh4[0], vh4[1]);
                    mma_bf16(o[nc * 2], pah, vl4[0], vl4[1]);
                    mma_bf16(o[nc * 2], pal, vh4[0], vh4[1]);
                    mma_bf16(o[nc * 2 + 1], pah, vh4[2], vh4[3]);
                    mma_bf16(o[nc * 2 + 1], pah, vl4[2], vl4[3]);
                    mma_bf16(o[nc * 2 + 1], pal, vh4[2], vh4[3]);
                }
            }

            NBAR_ARRIVE(4 + s % 3);  // stage free (non-blocking)
        }
    } else {
        // ---------------- producer warp ----------------
        for (int s = 0; s < S; s++) {
            if (s >= 3) NBAR_SYNC(4 + s % 3);                    // wait stage free
            attn_fill(sb, s % 3, s * 64, lane, b, h, Kh, Kl, Vh, Vl);
            if (s >= 2) { CP_WAIT(2); NBAR_ARRIVE(1 + (s - 2) % 3); }
        }
        CP_WAIT(1); NBAR_ARRIVE(1 + (S - 2) % 3);
        CP_WAIT(0); NBAR_ARRIVE(1 + (S - 1) % 3);
    }

    // ---- merge key-half partials ----
    __syncthreads();
    if (warp < 8 && (lane & 3) == 0) {
        sm_l[khf][r_lo] = l0; sm_l[khf][r_lo + 8] = l1;
    }
    __syncthreads();

    float* sO = (float*)(smem + ATT_O_MERGE);
    float rinv0 = 0.0f, rinv1 = 0.0f;
    if (warp < 8) {
        float lt0 = sm_l[0][r_lo] + sm_l[1][r_lo];
        float lt1 = sm_l[0][r_lo + 8] + sm_l[1][r_lo + 8];
        rinv0 = (lt0 > 0.0f) ? 1.0f / lt0 : 0.0f;
        rinv1 = (lt1 > 0.0f) ? 1.0f / lt1 : 0.0f;
        if (khf == 0) {
#pragma unroll
            for (int an = 0; an < 16; an++) {
                int col = an * 8 + (lane & 3) * 2;
                *(float2*)&sO[r_lo * 128 + col] = make_float2(o[an][0], o[an][1]);
                *(float2*)&sO[(r_lo + 8) * 128 + col] = make_float2(o[an][2], o[an][3]);
            }
        }
    }
    __syncthreads();
    if (warp < 8 && khf == 1) {
        __nv_bfloat16* oh0 = Oh + (size_t)(b * QL + q0 + r_lo) * DMODEL + h * HD;
        __nv_bfloat16* ol0 = Ol + (size_t)(b * QL + q0 + r_lo) * DMODEL + h * HD;
#pragma unroll
        for (int an = 0; an < 16; an++) {
            int col = an * 8 + (lane & 3) * 2;
            float2 p0 = *(const float2*)&sO[r_lo * 128 + col];
            float2 p1 = *(const float2*)&sO[(r_lo + 8) * 128 + col];
            float w0x = (p0.x + o[an][0]) * rinv0;
            float w0y = (p0.y + o[an][1]) * rinv0;
            float w1x = (p1.x + o[an][2]) * rinv1;
            float w1y = (p1.y + o[an][3]) * rinv1;
            uint32_t lo0, lo1;
            uint32_t h0 = pack_hi(w0x, w0y, lo0);
            uint32_t h1 = pack_hi(w1x, w1y, lo1);
            *(uint32_t*)&oh0[col] = h0;
            *(uint32_t*)&ol0[col] = lo0;
            *(uint32_t*)&oh0[8 * DMODEL + col] = h1;
            *(uint32_t*)&ol0[8 * DMODEL + col] = lo1;
        }
    }
}

// ---------------------------------------------------------------------------
extern "C" void kernel_launch(void* const* d_in, const int* in_sizes, int n_in,
                              void* d_out, int out_size)
{
    const float* xq = (const float*)d_in[0];
    const float* xk = (const float*)d_in[1];
    const float* xv = (const float*)d_in[2];
    const unsigned int* mask = (const unsigned int*)d_in[3];
    const float* Wq = (const float*)d_in[4];
    const float* bq = (const float*)d_in[5];
    const float* Wk = (const float*)d_in[6];
    const float* bk = (const float*)d_in[7];
    const float* Wv = (const float*)d_in[8];
    const float* bv = (const float*)d_in[9];
    const float* Wf = (const float*)d_in[10];
    const float* bf = (const float*)d_in[11];
    float* out = (float*)d_out;

    __nv_bfloat16 *Xqh, *Xql, *Xkh, *Xkl, *Xvh, *Xvl;
    __nv_bfloat16 *Wqh, *Wql, *Wkh, *Wkl, *Wvh, *Wvl, *Wfh, *Wfl;
    __nv_bfloat16 *Qh, *Qlp, *Khp, *Klp, *Vhp, *Vlp, *Ahp, *Alp;
    cudaGetSymbolAddress((void**)&Xqh, g_Xqh); cudaGetSymbolAddress((void**)&Xql, g_Xql);
    cudaGetSymbolAddress((void**)&Xkh, g_Xkh); cudaGetSymbolAddress((void**)&Xkl, g_Xkl);
    cudaGetSymbolAddress((void**)&Xvh, g_Xvh); cudaGetSymbolAddress((void**)&Xvl, g_Xvl);
    cudaGetSymbolAddress((void**)&Wqh, g_Wqh); cudaGetSymbolAddress((void**)&Wql, g_Wql);
    cudaGetSymbolAddress((void**)&Wkh, g_Wkh); cudaGetSymbolAddress((void**)&Wkl, g_Wkl);
    cudaGetSymbolAddress((void**)&Wvh, g_Wvh); cudaGetSymbolAddress((void**)&Wvl, g_Wvl);
    cudaGetSymbolAddress((void**)&Wfh, g_Wfh); cudaGetSymbolAddress((void**)&Wfl, g_Wfl);
    cudaGetSymbolAddress((void**)&Qh, g_Qh);   cudaGetSymbolAddress((void**)&Qlp, g_Ql);
    cudaGetSymbolAddress((void**)&Khp, g_Kh);  cudaGetSymbolAddress((void**)&Klp, g_Kl);
    cudaGetSymbolAddress((void**)&Vhp, g_Vh);  cudaGetSymbolAddress((void**)&Vlp, g_Vl);
    cudaGetSymbolAddress((void**)&Ahp, g_Ah);  cudaGetSymbolAddress((void**)&Alp, g_Al);

    static cudaStream_t sA = nullptr, sB = nullptr, sC = nullptr;
    static cudaEvent_t evFork = nullptr, evK = nullptr, evV = nullptr, evC = nullptr;
    static bool init_done = false;
    if (!init_done) {
        cudaFuncSetAttribute(attn_tc, cudaFuncAttributeMaxDynamicSharedMemorySize, ATT_SMEM);
        cudaFuncSetAttribute(gemm_bs<true>, cudaFuncAttributeMaxDynamicSharedMemorySize, G_SMEM);
        cudaFuncSetAttribute(gemm_bs<false>, cudaFuncAttributeMaxDynamicSharedMemorySize, G_SMEM);
        cudaStreamCreateWithFlags(&sA, cudaStreamNonBlocking);
        cudaStreamCreateWithFlags(&sB, cudaStreamNonBlocking);
        cudaStreamCreateWithFlags(&sC, cudaStreamNonBlocking);
        cudaEventCreateWithFlags(&evFork, cudaEventDisableTiming);
        cudaEventCreateWithFlags(&evK, cudaEventDisableTiming);
        cudaEventCreateWithFlags(&evV, cudaEventDisableTiming);
        cudaEventCreateWithFlags(&evC, cudaEventDisableTiming);
        init_done = true;
    }

    // Fork the three independent projection chains onto side streams.
    cudaEventRecord(evFork, 0);
    cudaStreamWaitEvent(sA, evFork, 0);
    cudaStreamWaitEvent(sB, evFork, 0);
    cudaStreamWaitEvent(sC, evFork, 0);

    // My 4th launch = gemmK (ncu -s 5 -c 1, offset 2) — control metric.
    split_f32<<<4096, 256, 0, sA>>>(xk, Xkh, Xkl, BSZ * KLEN * DMODEL / 4);    // 1
    split_f32<<<256, 256, 0, sA>>>(Wk, Wkh, Wkl, DMODEL * DMODEL / 4);         // 2
    split_f32<<<4096, 256, 0, sB>>>(xv, Xvh, Xvl, BSZ * KLEN * DMODEL / 4);    // 3
    gemm_bs<true><<<dim3(8, 128), 256, G_SMEM, sA>>>(Xkh, Xkl, Wkh, Wkl, bk,   // 4 <- profiled
        nullptr, Khp, Klp, BSZ * KLEN, DMODEL, DMODEL);
    split_f32<<<256, 256, 0, sB>>>(Wv, Wvh, Wvl, DMODEL * DMODEL / 4);         // 5
    gemm_bs<true><<<dim3(8, 128), 256, G_SMEM, sB>>>(Xvh, Xvl, Wvh, Wvl, bv,   // 6
        nullptr, Vhp, Vlp, BSZ * KLEN, DMODEL, DMODEL);
    split_f32<<<256, 256, 0, sC>>>(xq, Xqh, Xql, BSZ * QL * DMODEL / 4);       // 7
    split_f32<<<256, 256, 0, sC>>>(Wq, Wqh, Wql, DMODEL * DMODEL / 4);         // 8
    gemm_bs<true><<<dim3(8, 8), 256, G_SMEM, sC>>>(Xqh, Xql, Wqh, Wql, bq,     // 9
        nullptr, Qh, Qlp, BSZ * QL, DMODEL, DMODEL);
    split_f32<<<256, 256, 0, sC>>>(Wf, Wfh, Wfl, DMODEL * DMODEL / 4);         // 10

    // Join: attention needs Q, K, V; final gemm needs Wf (stream C).
    cudaEventRecord(evK, sA);
    cudaEventRecord(evV, sB);
    cudaEventRecord(evC, sC);
    cudaStreamWaitEvent(0, evK, 0);
    cudaStreamWaitEvent(0, evV, 0);
    cudaStreamWaitEvent(0, evC, 0);

    attn_tc<<<dim3(QL / 64, NH, BSZ), ATT_THREADS, ATT_SMEM>>>(Qh, Qlp,        // 11
        Khp, Klp, Vhp, Vlp, mask, Ahp, Alp);
    gemm_bs<false><<<dim3(8, 8), 256, G_SMEM>>>(Ahp, Alp, Wfh, Wfl, bf,        // 12
        out, nullptr, nullptr, BSZ * QL, DMODEL, DMODEL);
}

// round 16
// speedup vs baseline: 1.4121x; 1.4121x over previous
#include <cuda_runtime.h>
#include <cuda_bf16.h>
#include <cstdint>

// Problem constants
#define BSZ 2
#define QL 512
#define KLEN 8192
#define DMODEL 1024
#define NH 8
#define HD 128

// Scratch (allocation-free rule: __device__ globals)
__device__ __nv_bfloat16 g_Xqh[BSZ * QL * DMODEL],  g_Xql[BSZ * QL * DMODEL];
__device__ __nv_bfloat16 g_Xkh[BSZ * KLEN * DMODEL], g_Xkl[BSZ * KLEN * DMODEL];
__device__ __nv_bfloat16 g_Xvh[BSZ * KLEN * DMODEL], g_Xvl[BSZ * KLEN * DMODEL];
__device__ __nv_bfloat16 g_Wqh[DMODEL * DMODEL], g_Wql[DMODEL * DMODEL];
__device__ __nv_bfloat16 g_Wkh[DMODEL * DMODEL], g_Wkl[DMODEL * DMODEL];
__device__ __nv_bfloat16 g_Wvh[DMODEL * DMODEL], g_Wvl[DMODEL * DMODEL];
__device__ __nv_bfloat16 g_Wfh[DMODEL * DMODEL], g_Wfl[DMODEL * DMODEL];
__device__ __nv_bfloat16 g_Qh[BSZ * QL * DMODEL],  g_Ql[BSZ * QL * DMODEL];
__device__ __nv_bfloat16 g_Kh[BSZ * KLEN * DMODEL], g_Kl[BSZ * KLEN * DMODEL];
__device__ __nv_bfloat16 g_Vh[BSZ * KLEN * DMODEL], g_Vl[BSZ * KLEN * DMODEL];
__device__ __nv_bfloat16 g_Ah[BSZ * QL * DMODEL],  g_Al[BSZ * QL * DMODEL];

// ===========================================================================
// Helpers
// ===========================================================================
__device__ __forceinline__ uint32_t smem_u32(const void* p) {
    uint32_t a;
    asm("{ .reg .u64 t; cvta.to.shared.u64 t, %1; cvt.u32.u64 %0, t; }"
        : "=r"(a) : "l"(p));
    return a;
}

__device__ __forceinline__ void mma_bf16(float* d, const uint32_t* a,
                                         uint32_t b0, uint32_t b1) {
    asm volatile(
        "mma.sync.aligned.m16n8k16.row.col.f32.bf16.bf16.f32 "
        "{%0,%1,%2,%3}, {%4,%5,%6,%7}, {%8,%9}, {%0,%1,%2,%3};"
        : "+f"(d[0]), "+f"(d[1]), "+f"(d[2]), "+f"(d[3])
        : "r"(a[0]), "r"(a[1]), "r"(a[2]), "r"(a[3]), "r"(b0), "r"(b1));
}

__device__ __forceinline__ void ldsm4(uint32_t* r, uint32_t addr) {
    asm volatile("ldmatrix.sync.aligned.m8n8.x4.shared.b16 {%0,%1,%2,%3}, [%4];"
                 : "=r"(r[0]), "=r"(r[1]), "=r"(r[2]), "=r"(r[3]) : "r"(addr));
}

__device__ __forceinline__ void ldsm4t(uint32_t* r, uint32_t addr) {
    asm volatile("ldmatrix.sync.aligned.m8n8.x4.trans.shared.b16 {%0,%1,%2,%3}, [%4];"
                 : "=r"(r[0]), "=r"(r[1]), "=r"(r[2]), "=r"(r[3]) : "r"(addr));
}

__device__ __forceinline__ uint32_t pack_hi(float x, float y, uint32_t& lo) {
    __nv_bfloat162 h = __float22bfloat162_rn(make_float2(x, y));
    float2 f = __bfloat1622float2(h);
    __nv_bfloat162 l = __float22bfloat162_rn(make_float2(x - f.x, y - f.y));
    lo = *reinterpret_cast<uint32_t*>(&l);
    return *reinterpret_cast<uint32_t*>(&h);
}

__device__ __forceinline__ void cp16(uint32_t dst, const void* src) {
    asm volatile("cp.async.cg.shared.global [%0], [%1], 16;" :: "r"(dst), "l"(src));
}
#define CP_COMMIT() asm volatile("cp.async.commit_group;")
#define CP_WAIT(n)  asm volatile("cp.async.wait_group %0;" :: "n"(n))

// ===========================================================================
// Split: fp32 -> (hi bf16, lo bf16), MLP=4 superstep
// ===========================================================================
__global__ __launch_bounds__(256) void split_f32(
    const float* __restrict__ in, __nv_bfloat16* __restrict__ oh,
    __nv_bfloat16* __restrict__ ol, int n4)
{
    const int stride = gridDim.x * blockDim.x;
    for (int i = blockIdx.x * blockDim.x + threadIdx.x; i < n4; i += 4 * stride) {
        float4 v[4];
        int idx[4];
        int cnt = 0;
#pragma unroll
        for (int j = 0; j < 4; j++) {
            int ii = i + j * stride;
            if (ii < n4) { v[cnt] = ((const float4*)in)[ii]; idx[cnt] = ii; cnt++; }
        }
#pragma unroll
        for (int j = 0; j < 4; j++) {
            if (j < cnt) {
                uint32_t l0, l1;
                uint32_t h0 = pack_hi(v[j].x, v[j].y, l0);
                uint32_t h1 = pack_hi(v[j].z, v[j].w, l1);
                ((uint2*)oh)[idx[j]] = make_uint2(h0, h1);
                ((uint2*)ol)[idx[j]] = make_uint2(l0, l1);
            }
        }
    }
}

// ===========================================================================
// Split-bf16 GEMM, cp.async 3-stage pipeline, 2 CTAs/SM.
// ===========================================================================
#define G_STAGE 32768
#define G_SMEM  (3 * G_STAGE)

__device__ __forceinline__ uint32_t g_ldaddr(uint32_t base, int row0, int chunk0, int lane) {
    int r = row0 + (lane & 7) + ((lane >> 3) & 1) * 8;
    int c = (chunk0 + (lane >> 4)) ^ ((r >> 1) & 3);
    return base + (uint32_t)(r * 4 + c) * 16;
}

__device__ __forceinline__ void gemm_stage(
    uint32_t sb, int st, int kt, int tid, int bm, int bn, int K,
    const __nv_bfloat16* Ah, const __nv_bfloat16* Al,
    const __nv_bfloat16* Bh, const __nv_bfloat16* Bl)
{
#pragma unroll
    for (int i = 0; i < 8; i++) {
        int ci = tid + i * 256;
        int arr = ci >> 9, cj = ci & 511;
        int row = cj >> 2, c = cj & 3;
        const __nv_bfloat16* g = (arr == 0) ? Ah : (arr == 1) ? Al
                               : (arr == 2) ? Bh : Bl;
        int rb = (arr < 2) ? bm : bn;
        const void* src = g + (size_t)(rb + row) * K + kt + c * 8;
        uint32_t dst = sb + st * G_STAGE + arr * 8192 +
                       (uint32_t)((row << 2) + (c ^ ((row >> 1) & 3))) * 16;
        cp16(dst, src);
    }
    CP_COMMIT();
}

template <bool SPLIT_OUT>
__global__ __launch_bounds__(256, 2) void gemm_bs(
    const __nv_bfloat16* __restrict__ Ah, const __nv_bfloat16* __restrict__ Al,
    const __nv_bfloat16* __restrict__ Bh, const __nv_bfloat16* __restrict__ Bl,
    const float* __restrict__ bias, float* __restrict__ C,
    __nv_bfloat16* __restrict__ Ch, __nv_bfloat16* __restrict__ Cl,
    int M, int N, int K)
{
    extern __shared__ char smem[];
    const uint32_t sb = smem_u32(smem);
    const int tid = threadIdx.x;
    const int lane = tid & 31, warp = tid >> 5;
    const int wm = warp >> 2, wn = warp & 3;
    const int bm = blockIdx.y * 128, bn = blockIdx.x * 128;

    float acc[4][4][4];
#pragma unroll
    for (int i = 0; i < 4; i++)
#pragma unroll
        for (int j = 0; j < 4; j++)
#pragma unroll
            for (int q = 0; q < 4; q++) acc[i][j][q] = 0.0f;

    const int S = K / 32;
    gemm_stage(sb, 0, 0, tid, bm, bn, K, Ah, Al, Bh, Bl);
    gemm_stage(sb, 1, 32, tid, bm, bn, K, Ah, Al, Bh, Bl);

    for (int s = 0; s < S; s++) {
        if (s + 1 < S) { CP_WAIT(1); } else { CP_WAIT(0); }
        __syncthreads();
        if (s + 2 < S)
            gemm_stage(sb, (s + 2) % 3, (s + 2) * 32, tid, bm, bn, K, Ah, Al, Bh, Bl);

        const uint32_t stb = sb + (s % 3) * G_STAGE;
        const uint32_t aAh = stb, aAl = stb + 8192;
        const uint32_t aBh = stb + 16384, aBl = stb + 24576;
#pragma unroll
        for (int ks = 0; ks < 2; ks++) {
            uint32_t ah[4][4], al[4][4], bh[2][4], bl[2][4];
#pragma unroll
            for (int am = 0; am < 4; am++) {
                ldsm4(ah[am], g_ldaddr(aAh, wm * 64 + am * 16, ks * 2, lane));
                ldsm4(al[am], g_ldaddr(aAl, wm * 64 + am * 16, ks * 2, lane));
            }
#pragma unroll
            for (int nb = 0; nb < 2; nb++) {
                ldsm4(bh[nb], g_ldaddr(aBh, wn * 32 + nb * 16, ks * 2, lane));
                ldsm4(bl[nb], g_ldaddr(aBl, wn * 32 + nb * 16, ks * 2, lane));
            }
#pragma unroll
            for (int am = 0; am < 4; am++)
#pragma unroll
                for (int an = 0; an < 4; an++) {
                    const int nb = an >> 1, si = an & 1;
                    mma_bf16(acc[am][an], ah[am], bh[nb][si], bh[nb][si + 2]);
                    mma_bf16(acc[am][an], ah[am], bl[nb][si], bl[nb][si + 2]);
                    mma_bf16(acc[am][an], al[am], bh[nb][si], bh[nb][si + 2]);
                }
        }
    }

#pragma unroll
    for (int am = 0; am < 4; am++) {
        const int r0 = bm + wm * 64 + am * 16 + (lane >> 2);
#pragma unroll
        for (int an = 0; an < 4; an++) {
            const int col = bn + wn * 32 + an * 8 + (lane & 3) * 2;
            float2 b01 = *(const float2*)&bias[col];
            float v0 = acc[am][an][0] + b01.x, v1 = acc[am][an][1] + b01.y;
            float v2 = acc[am][an][2] + b01.x, v3 = acc[am][an][3] + b01.y;
            if (SPLIT_OUT) {
                uint32_t lo0, lo1;
                uint32_t h0 = pack_hi(v0, v1, lo0);
                uint32_t h1 = pack_hi(v2, v3, lo1);
                *(uint32_t*)&Ch[(size_t)r0 * N + col] = h0;
                *(uint32_t*)&Cl[(size_t)r0 * N + col] = lo0;
                *(uint32_t*)&Ch[(size_t)(r0 + 8) * N + col] = h1;
                *(uint32_t*)&Cl[(size_t)(r0 + 8) * N + col] = lo1;
            } else {
                *(float2*)&C[(size_t)r0 * N + col] = make_float2(v0, v1);
                *(float2*)&C[(size_t)(r0 + 8) * N + col] = make_float2(v2, v3);
            }
        }
    }
}

// ===========================================================================
// Tensor-core flash attention, 3-stage cp.async pipeline (full-block fills,
// one barrier per iteration — the round-13 structure that measured best).
// Fixed-max softmax; Q hi AND lo fragments register-resident.
// ===========================================================================
#define ATT_Q_H 0
#define ATT_Q_L 16384
#define ATT_ST0 32768
#define ATT_STAGE 65536
#define ATT_SMEM (32768 + 3 * ATT_STAGE)   // 224 KB
#define ATT_O_MERGE 32768   // fp32 [64][128] overlay after mainloop

__device__ __forceinline__ uint32_t taddr(uint32_t base, int r, int c) {
    return base + (uint32_t)((r << 4) + (c ^ (r & 7))) * 16;
}
__device__ __forceinline__ uint32_t ab_addr(uint32_t base, int row0, int c0, int lane) {
    int r = row0 + (lane & 7) + ((lane >> 3) & 1) * 8;
    int c = c0 + (lane >> 4);
    return taddr(base, r, c);
}
__device__ __forceinline__ uint32_t v_addr(uint32_t base, int row0, int c0, int lane) {
    int r = row0 + (lane & 15);
    int c = c0 + (lane >> 4);
    return taddr(base, r, c);
}

__device__ __forceinline__ void attn_stage(
    uint32_t sb, int st, int k0, int tid, int b, int h,
    const __nv_bfloat16* Kh, const __nv_bfloat16* Kl,
    const __nv_bfloat16* Vh, const __nv_bfloat16* Vl)
{
#pragma unroll
    for (int i = 0; i < 16; i++) {
        int ci = tid + i * 256;
        int arr = ci >> 10, cj = ci & 1023;
        int row = cj >> 4, c = cj & 15;
        const __nv_bfloat16* g = (arr == 0) ? Kh : (arr == 1) ? Kl
                               : (arr == 2) ? Vh : Vl;
        const void* src = g + (size_t)(b * KLEN + k0 + row) * DMODEL + h * HD + c * 8;
        uint32_t dst = sb + ATT_ST0 + st * ATT_STAGE + arr * 16384 +
                       (uint32_t)((row << 4) + (c ^ (row & 7))) * 16;
        cp16(dst, src);
    }
    CP_COMMIT();
}

__global__ __launch_bounds__(256) void attn_tc(
    const __nv_bfloat16* __restrict__ Qh, const __nv_bfloat16* __restrict__ Ql,
    const __nv_bfloat16* __restrict__ Kh, const __nv_bfloat16* __restrict__ Kl,
    const __nv_bfloat16* __restrict__ Vh, const __nv_bfloat16* __restrict__ Vl,
    const unsigned int* __restrict__ mask,
    __nv_bfloat16* __restrict__ Oh, __nv_bfloat16* __restrict__ Ol)
{
    extern __shared__ char smem[];
    __shared__ float sm_l[2][64];
    const uint32_t sb = smem_u32(smem);
    const int tid = threadIdx.x, lane = tid & 31, warp = tid >> 5;
    const int rg = warp & 3, khf = warp >> 2;
    const int b = blockIdx.z, h = blockIdx.y;
    const int q0 = blockIdx.x * 64;

    // stage Q hi/lo
#pragma unroll
    for (int i = 0; i < 4; i++) {
        int ci = tid + i * 256;
        int r = ci >> 4, c = ci & 15;
        size_t g = ((size_t)(b * QL + q0 + r) * DMODEL + h * HD) / 8 + c;
        uint32_t d = (uint32_t)((r << 4) + (c ^ (r & 7))) * 16;
        *(uint4*)(smem + ATT_Q_H + d) = ((const uint4*)Qh)[g];
        *(uint4*)(smem + ATT_Q_L + d) = ((const uint4*)Ql)[g];
    }
    const int S = KLEN / 64;
    attn_stage(sb, 0, 0, tid, b, h, Kh, Kl, Vh, Vl);
    attn_stage(sb, 1, 64, tid, b, h, Kh, Kl, Vh, Vl);
    __syncthreads();

    // Q hi AND lo fragments -> registers (reused all 128 iterations)
    uint32_t qhr[8][4], qlr[8][4];
#pragma unroll
    for (int ks = 0; ks < 8; ks++) {
        ldsm4(qhr[ks], ab_addr(sb + ATT_Q_H, rg * 16, ks * 2, lane));
        ldsm4(qlr[ks], ab_addr(sb + ATT_Q_L, rg * 16, ks * 2, lane));
    }

    float o[16][4];
#pragma unroll
    for (int n = 0; n < 16; n++)
#pragma unroll
        for (int j = 0; j < 4; j++) o[n][j] = 0.0f;
    float l0 = 0.0f, l1 = 0.0f;
    const float scale2 = 0.08838834764831845f * 1.4426950408889634f;  // scale*log2e
    const float FIXM = 16.0f;  // fixed softmax bias (cancels in O/l)

    const int r_lo = rg * 16 + (lane >> 2);
    const unsigned int* mrow0 = mask + (size_t)(b * QL + q0 + r_lo) * KLEN;
    const unsigned int* mrow1 = mrow0 + 8 * (size_t)KLEN;

    for (int s = 0; s < S; s++) {
        const int k0 = s * 64;

        // hoisted mask loads
        uint2 mka[4], mkb[4];
#pragma unroll
        for (int an = 0; an < 4; an++) {
            int col = k0 + khf * 32 + an * 8 + (lane & 3) * 2;
            mka[an] = *(const uint2*)&mrow0[col];
            mkb[an] = *(const uint2*)&mrow1[col];
        }

        if (s + 1 < S) { CP_WAIT(1); } else { CP_WAIT(0); }
        __syncthreads();
        if (s + 2 < S)
            attn_stage(sb, (s + 2) % 3, (s + 2) * 64, tid, b, h, Kh, Kl, Vh, Vl);

        const uint32_t stb = sb + ATT_ST0 + (s % 3) * ATT_STAGE;
        const uint32_t aKh = stb, aKl = stb + 16384;
        const uint32_t aVh = stb + 32768, aVl = stb + 49152;

        // ---- QK^T, split 3-term ----
        float s4[4][4];
#pragma unroll
        for (int an = 0; an < 4; an++)
#pragma unroll
            for (int j = 0; j < 4; j++) s4[an][j] = 0.0f;

#pragma unroll
        for (int ks = 0; ks < 8; ks++) {
            uint32_t kbh0[4], kbh1[4], kbl0[4], kbl1[4];
            ldsm4(kbh0, ab_addr(aKh, khf * 32, ks * 2, lane));
            ldsm4(kbh1, ab_addr(aKh, khf * 32 + 16, ks * 2, lane));
            ldsm4(kbl0, ab_addr(aKl, khf * 32, ks * 2, lane));
            ldsm4(kbl1, ab_addr(aKl, khf * 32 + 16, ks * 2, lane));
#pragma unroll
            for (int an = 0; an < 4; an++) {
                const uint32_t* bh = (an < 2) ? kbh0 : kbh1;
                const uint32_t* bl = (an < 2) ? kbl0 : kbl1;
                const int si = an & 1;
                mma_bf16(s4[an], qhr[ks], bh[si], bh[si + 2]);
                mma_bf16(s4[an], qhr[ks], bl[si], bl[si + 2]);
                mma_bf16(s4[an], qlr[ks], bh[si], bh[si + 2]);
            }
        }

        // ---- fixed-max softmax ----
        float ps0 = 0.0f, ps1 = 0.0f;
#pragma unroll
        for (int an = 0; an < 4; an++) {
            s4[an][0] = mka[an].x ? exp2f(fmaf(s4[an][0], scale2, -FIXM)) : 0.0f;
            s4[an][1] = mka[an].y ? exp2f(fmaf(s4[an][1], scale2, -FIXM)) : 0.0f;
            s4[an][2] = mkb[an].x ? exp2f(fmaf(s4[an][2], scale2, -FIXM)) : 0.0f;
            s4[an][3] = mkb[an].y ? exp2f(fmaf(s4[an][3], scale2, -FIXM)) : 0.0f;
            ps0 += s4[an][0] + s4[an][1];
            ps1 += s4[an][2] + s4[an][3];
        }
        ps0 += __shfl_xor_sync(0xffffffffu, ps0, 1);
        ps0 += __shfl_xor_sync(0xffffffffu, ps0, 2);
        ps1 += __shfl_xor_sync(0xffffffffu, ps1, 1);
        ps1 += __shfl_xor_sync(0xffffffffu, ps1, 2);
        l0 += ps0; l1 += ps1;

        // ---- P @ V, split 3-term ----
#pragma unroll
        for (int ks2 = 0; ks2 < 2; ks2++) {
            uint32_t pah[4], pal[4];
            pah[0] = pack_hi(s4[ks2 * 2][0], s4[ks2 * 2][1], pal[0]);
            pah[1] = pack_hi(s4[ks2 * 2][2], s4[ks2 * 2][3], pal[1]);
            pah[2] = pack_hi(s4[ks2 * 2 + 1][0], s4[ks2 * 2 + 1][1], pal[2]);
            pah[3] = pack_hi(s4[ks2 * 2 + 1][2], s4[ks2 * 2 + 1][3], pal[3]);
#pragma unroll
            for (int nc = 0; nc < 8; nc++) {
                uint32_t vh4[4], vl4[4];
                ldsm4t(vh4, v_addr(aVh, khf * 32 + ks2 * 16, nc * 2, lane));
                ldsm4t(vl4, v_addr(aVl, khf * 32 + ks2 * 16, nc * 2, lane));
                mma_bf16(o[nc * 2], pah, vh4[0], vh4[1]);
                mma_bf16(o[nc * 2], pah, vl4[0], vl4[1]);
                mma_bf16(o[nc * 2], pal, vh4[0], vh4[1]);
                mma_bf16(o[nc * 2 + 1], pah, vh4[2], vh4[3]);
                mma_bf16(o[nc * 2 + 1], pah, vl4[2], vl4[3]);
                mma_bf16(o[nc * 2 + 1], pal, vh4[2], vh4[3]);
            }
        }
    }

    // ---- merge key-half partials ----
    __syncthreads();
    if ((lane & 3) == 0) {
        sm_l[khf][r_lo] = l0; sm_l[khf][r_lo + 8] = l1;
    }
    __syncthreads();

    float lt0 = sm_l[0][r_lo] + sm_l[1][r_lo];
    float lt1 = sm_l[0][r_lo + 8] + sm_l[1][r_lo + 8];
    float rinv0 = (lt0 > 0.0f) ? 1.0f / lt0 : 0.0f;
    float rinv1 = (lt1 > 0.0f) ? 1.0f / lt1 : 0.0f;

    float* sO = (float*)(smem + ATT_O_MERGE);
    if (khf == 0) {
#pragma unroll
        for (int an = 0; an < 16; an++) {
            int col = an * 8 + (lane & 3) * 2;
            *(float2*)&sO[r_lo * 128 + col] = make_float2(o[an][0], o[an][1]);
            *(float2*)&sO[(r_lo + 8) * 128 + col] = make_float2(o[an][2], o[an][3]);
        }
    }
    __syncthreads();
    if (khf == 1) {
        __nv_bfloat16* oh0 = Oh + (size_t)(b * QL + q0 + r_lo) * DMODEL + h * HD;
        __nv_bfloat16* ol0 = Ol + (size_t)(b * QL + q0 + r_lo) * DMODEL + h * HD;
#pragma unroll
        for (int an = 0; an < 16; an++) {
            int col = an * 8 + (lane & 3) * 2;
            float2 p0 = *(const float2*)&sO[r_lo * 128 + col];
            float2 p1 = *(const float2*)&sO[(r_lo + 8) * 128 + col];
            float w0x = (p0.x + o[an][0]) * rinv0;
            float w0y = (p0.y + o[an][1]) * rinv0;
            float w1x = (p1.x + o[an][2]) * rinv1;
            float w1y = (p1.y + o[an][3]) * rinv1;
            uint32_t lo0, lo1;
            uint32_t h0 = pack_hi(w0x, w0y, lo0);
            uint32_t h1 = pack_hi(w1x, w1y, lo1);
            *(uint32_t*)&oh0[col] = h0;
            *(uint32_t*)&ol0[col] = lo0;
            *(uint32_t*)&oh0[8 * DMODEL + col] = h1;
            *(uint32_t*)&ol0[8 * DMODEL + col] = lo1;
        }
    }
}

// ---------------------------------------------------------------------------
extern "C" void kernel_launch(void* const* d_in, const int* in_sizes, int n_in,
                              void* d_out, int out_size)
{
    const float* xq = (const float*)d_in[0];
    const float* xk = (const float*)d_in[1];
    const float* xv = (const float*)d_in[2];
    const unsigned int* mask = (const unsigned int*)d_in[3];
    const float* Wq = (const float*)d_in[4];
    const float* bq = (const float*)d_in[5];
    const float* Wk = (const float*)d_in[6];
    const float* bk = (const float*)d_in[7];
    const float* Wv = (const float*)d_in[8];
    const float* bv = (const float*)d_in[9];
    const float* Wf = (const float*)d_in[10];
    const float* bf = (const float*)d_in[11];
    float* out = (float*)d_out;

    __nv_bfloat16 *Xqh, *Xql, *Xkh, *Xkl, *Xvh, *Xvl;
    __nv_bfloat16 *Wqh, *Wql, *Wkh, *Wkl, *Wvh, *Wvl, *Wfh, *Wfl;
    __nv_bfloat16 *Qh, *Qlp, *Khp, *Klp, *Vhp, *Vlp, *Ahp, *Alp;
    cudaGetSymbolAddress((void**)&Xqh, g_Xqh); cudaGetSymbolAddress((void**)&Xql, g_Xql);
    cudaGetSymbolAddress((void**)&Xkh, g_Xkh); cudaGetSymbolAddress((void**)&Xkl, g_Xkl);
    cudaGetSymbolAddress((void**)&Xvh, g_Xvh); cudaGetSymbolAddress((void**)&Xvl, g_Xvl);
    cudaGetSymbolAddress((void**)&Wqh, g_Wqh); cudaGetSymbolAddress((void**)&Wql, g_Wql);
    cudaGetSymbolAddress((void**)&Wkh, g_Wkh); cudaGetSymbolAddress((void**)&Wkl, g_Wkl);
    cudaGetSymbolAddress((void**)&Wvh, g_Wvh); cudaGetSymbolAddress((void**)&Wvl, g_Wvl);
    cudaGetSymbolAddress((void**)&Wfh, g_Wfh); cudaGetSymbolAddress((void**)&Wfl, g_Wfl);
    cudaGetSymbolAddress((void**)&Qh, g_Qh);   cudaGetSymbolAddress((void**)&Qlp, g_Ql);
    cudaGetSymbolAddress((void**)&Khp, g_Kh);  cudaGetSymbolAddress((void**)&Klp, g_Kl);
    cudaGetSymbolAddress((void**)&Vhp, g_Vh);  cudaGetSymbolAddress((void**)&Vlp, g_Vl);
    cudaGetSymbolAddress((void**)&Ahp, g_Ah);  cudaGetSymbolAddress((void**)&Alp, g_Al);

    static cudaStream_t sA = nullptr, sB = nullptr, sC = nullptr;
    static cudaEvent_t evFork = nullptr, evK = nullptr, evV = nullptr, evC = nullptr;
    static bool init_done = false;
    if (!init_done) {
        cudaFuncSetAttribute(attn_tc, cudaFuncAttributeMaxDynamicSharedMemorySize, ATT_SMEM);
        cudaFuncSetAttribute(gemm_bs<true>, cudaFuncAttributeMaxDynamicSharedMemorySize, G_SMEM);
        cudaFuncSetAttribute(gemm_bs<false>, cudaFuncAttributeMaxDynamicSharedMemorySize, G_SMEM);
        cudaStreamCreateWithFlags(&sA, cudaStreamNonBlocking);
        cudaStreamCreateWithFlags(&sB, cudaStreamNonBlocking);
        cudaStreamCreateWithFlags(&sC, cudaStreamNonBlocking);
        cudaEventCreateWithFlags(&evFork, cudaEventDisableTiming);
        cudaEventCreateWithFlags(&evK, cudaEventDisableTiming);
        cudaEventCreateWithFlags(&evV, cudaEventDisableTiming);
        cudaEventCreateWithFlags(&evC, cudaEventDisableTiming);
        init_done = true;
    }

    // Fork the three independent projection chains onto side streams.
    cudaEventRecord(evFork, 0);
    cudaStreamWaitEvent(sA, evFork, 0);
    cudaStreamWaitEvent(sB, evFork, 0);
    cudaStreamWaitEvent(sC, evFork, 0);

    // My 4th launch = gemmK (ncu -s 5 -c 1, offset 2) — control metric.
    split_f32<<<4096, 256, 0, sA>>>(xk, Xkh, Xkl, BSZ * KLEN * DMODEL / 4);    // 1
    split_f32<<<256, 256, 0, sA>>>(Wk, Wkh, Wkl, DMODEL * DMODEL / 4);         // 2
    split_f32<<<4096, 256, 0, sB>>>(xv, Xvh, Xvl, BSZ * KLEN * DMODEL / 4);    // 3
    gemm_bs<true><<<dim3(8, 128), 256, G_SMEM, sA>>>(Xkh, Xkl, Wkh, Wkl, bk,   // 4 <- profiled
        nullptr, Khp, Klp, BSZ * KLEN, DMODEL, DMODEL);
    split_f32<<<256, 256, 0, sB>>>(Wv, Wvh, Wvl, DMODEL * DMODEL / 4);         // 5
    gemm_bs<true><<<dim3(8, 128), 256, G_SMEM, sB>>>(Xvh, Xvl, Wvh, Wvl, bv,   // 6
        nullptr, Vhp, Vlp, BSZ * KLEN, DMODEL, DMODEL);
    split_f32<<<256, 256, 0, sC>>>(xq, Xqh, Xql, BSZ * QL * DMODEL / 4);       // 7
    split_f32<<<256, 256, 0, sC>>>(Wq, Wqh, Wql, DMODEL * DMODEL / 4);         // 8
    gemm_bs<true><<<dim3(8, 8), 256, G_SMEM, sC>>>(Xqh, Xql, Wqh, Wql, bq,     // 9
        nullptr, Qh, Qlp, BSZ * QL, DMODEL, DMODEL);
    split_f32<<<256, 256, 0, sC>>>(Wf, Wfh, Wfl, DMODEL * DMODEL / 4);         // 10

    // Join: attention needs Q, K, V; final gemm needs Wf (stream C).
    cudaEventRecord(evK, sA);
    cudaEventRecord(evV, sB);
    cudaEventRecord(evC, sC);
    cudaStreamWaitEvent(0, evK, 0);
    cudaStreamWaitEvent(0, evV, 0);
    cudaStreamWaitEvent(0, evC, 0);

    attn_tc<<<dim3(QL / 64, NH, BSZ), 256, ATT_SMEM>>>(Qh, Qlp, Khp, Klp,      // 11
        Vhp, Vlp, mask, Ahp, Alp);
    gemm_bs<false><<<dim3(8, 8), 256, G_SMEM>>>(Ahp, Alp, Wfh, Wfl, bf,        // 12
        out, nullptr, nullptr, BSZ * QL, DMODEL, DMODEL);
}